// round 9
// baseline (speedup 1.0000x reference)
#include <cuda_runtime.h>

#define NT    256
#define NCLS  16
#define DIM   128
#define NR    8192
#define NBA   256
#define RPA   (NR / NBA)     // 32 rows per A-block
#define HPA   (RPA / 2)      // 16 feature values held per thread
#define NBB   256
#define RPBB  (NR / NBB)     // 32 rows per B-block
#define EPS   1e-6
#define MARGIN 10.0
#define SCALE_F 4294967296.0           // 2^32 fixed-point scale for Fsum
#define INV_F   (1.0 / 4294967296.0)
#define SCALE_S 16777216.0             // 2^24 for sum-of-squares
#define INV_S   (1.0 / 16777216.0)

// ---- persistent scratch (no allocation allowed) ----
__device__ unsigned long long g_aF[NCLS][DIM];  // fixed-point class feature sums
__device__ unsigned long long g_aS[NCLS];       // fixed-point class sum-of-squares
__device__ int      g_aC[NCLS];                 // class counts
__device__ float    g_G[NCLS][DIM];             // precomputed G vectors (kA tail -> kB)
__device__ float    g_Al[NCLS], g_Be[NCLS], g_Vl[NCLS];
__device__ unsigned g_cA, g_cB;                 // election counters (monotone)
__device__ double   g_bL[NBB], g_bV[NBB];       // per-block loss/valid partials

// ================= kernel A: class stats + (elected) G build ================
__global__ void __launch_bounds__(NT, 2)
kA_stats(const float* __restrict__ f, const int* __restrict__ labw) {
    __shared__ float s1[2][NCLS][DIM];   // partials | tail: sF reuse (s1[0])
    __shared__ float s2[2][NCLS][DIM];
    __shared__ int   sLab[RPA];
    __shared__ float sPS[NCLS][8];
    __shared__ int   sPC[NCLS][8];
    __shared__ float sTot[DIM];
    __shared__ float sAv[NCLS], sBv[NCLS], sSq[NCLS];
    __shared__ int   sCt[NCLS];
    __shared__ double sSqTotD;
    __shared__ int   sLast;

    const int tid = threadIdx.x;
    const int b   = blockIdx.x;
    const int r0  = b * RPA;
    const int dim = tid & (DIM - 1);
    const int h   = tid >> 7;

    // one dependent DRAM round: features + detect words + both label layouts
    float v[HPA];
#pragma unroll
    for (int it = 0; it < HPA; ++it)
        v[it] = f[(size_t)(r0 + 2 * it + h) * DIM + dim];
    int l32 = 0, l64 = 0;
    if (tid < RPA) {
        l32 = labw[r0 + tid];
        l64 = labw[(r0 + tid) << 1];
    }
    int acc = labw[2 * tid + 1] | labw[2 * (tid + NT) + 1];
    const int is64 = (__syncthreads_or(acc) == 0);
    if (tid < RPA) sLab[tid] = (is64 ? l64 : l32) & (NCLS - 1);
    for (int i = tid; i < 2 * NCLS * DIM; i += NT) {
        (&s1[0][0][0])[i] = 0.f;
        (&s2[0][0][0])[i] = 0.f;
    }
    __syncthreads();

    // per-block class partials (16-link smem chain per thread)
#pragma unroll
    for (int it = 0; it < HPA; ++it) {
        const int k = sLab[2 * it + h];
        s1[h][k][dim] += v[it];
        s2[h][k][dim] = fmaf(v[it], v[it], s2[h][k][dim]);
    }
    __syncthreads();

    // exact fixed-point commit (spread addresses; integer atomics => deterministic)
    if (tid < DIM) {
#pragma unroll
        for (int k = 0; k < NCLS; ++k) {
            const double p = (double)(s1[0][k][tid] + s1[1][k][tid]);
            atomicAdd(&g_aF[k][tid], (unsigned long long)__double2ll_rn(p * SCALE_F));
        }
    } else {
        const int t = tid - DIM, k = t >> 3, part = t & 7;
        float s = 0.f;
#pragma unroll
        for (int d = 0; d < 16; ++d) {
            const int dd = part * 16 + d;
            s += s2[0][k][dd] + s2[1][k][dd];
        }
        sPS[k][part] = s;
        int c = 0;
#pragma unroll
        for (int r = 0; r < 4; ++r) c += (sLab[part * 4 + r] == k);
        sPC[k][part] = c;
    }
    __syncthreads();
    if (tid < NCLS) {
        float s = 0.f; int c = 0;
#pragma unroll
        for (int p = 0; p < 8; ++p) { s += sPS[tid][p]; c += sPC[tid][p]; }
        atomicAdd(&g_aS[tid], (unsigned long long)__double2ll_rn((double)s * SCALE_S));
        atomicAdd(&g_aC[tid], c);
    }

    // ---- elect LAST block: build G/consts, reset accumulators -----------------
    __threadfence();
    __syncthreads();
    if (tid == 0) {
        const unsigned tk = atomicAdd(&g_cA, 1u);
        sLast = (((tk + 1u) & (NBA - 1u)) == 0u);   // monotone: replay-safe
    }
    __syncthreads();

    if (sLast) {
        __threadfence();                            // acquire: all commits visible
        float* sF = &s1[0][0][0];                   // reuse 8KB of smem
        for (int i = tid; i < NCLS * DIM; i += NT) {
            const long long a = (long long)__ldcg(&g_aF[0][0] + i);
            sF[i] = (float)((double)a * INV_F);
        }
        if (tid < NCLS) {
            sSq[tid] = (float)((double)(long long)__ldcg(&g_aS[tid]) * INV_S);
            sCt[tid] = __ldcg(&g_aC[tid]);
        }
        __syncthreads();
        // reset accumulators for the next graph replay (captured above)
        for (int i = tid; i < NCLS * DIM; i += NT) (&g_aF[0][0])[i] = 0ull;
        if (tid < NCLS) { g_aS[tid] = 0ull; g_aC[tid] = 0; }
        if (tid < DIM) {
            float t = 0.f;
#pragma unroll
            for (int k = 0; k < NCLS; ++k) t += sF[k * DIM + tid];
            sTot[tid] = t;
        } else if (tid == NT - 1) {
            double st = 0.0;
#pragma unroll
            for (int k = 0; k < NCLS; ++k) st += (double)sSq[k];
            sSqTotD = st;
        }
        __syncthreads();
        if (tid < NCLS) {
            const double cnt = (double)sCt[tid];
            const double c   = cnt - 1.0;
            const double Bv  = 1.0 / ((double)NR - c - 1.0 + EPS);
            const double Av  = 1.0 / (c + EPS) + Bv;
            sAv[tid] = (float)Av;
            sBv[tid] = (float)Bv;
            g_Al[tid] = (float)(cnt * Av - (double)NR * Bv);
            g_Be[tid] = (float)((double)sSq[tid] * Av - sSqTotD * Bv + MARGIN);
            g_Vl[tid] = (sCt[tid] > 1) ? 1.f : 0.f;
        }
        __syncthreads();
        for (int i = tid; i < NCLS * DIM; i += NT) {
            const int k = i >> 7, d = i & (DIM - 1);
            g_G[k][d] = sAv[k] * sF[k * DIM + d] - sBv[k] * sTot[d];
        }
    }
}

// ======================= kernel B: per-row loss + reduce ====================
__global__ void __launch_bounds__(NT)
kB_loss(const float* __restrict__ f, const int* __restrict__ labw,
        float* __restrict__ out) {
    __shared__ __align__(16) float sG[NCLS][DIM];
    __shared__ float sAl[NCLS], sBe[NCLS], sVl[NCLS];
    __shared__ int   sLab[RPBB];
    __shared__ float sWL[8], sWV[8];
    __shared__ int   sLast;
    __shared__ __align__(16) double sR[2][NBB / 2];

    const int tid  = threadIdx.x;
    const int b    = blockIdx.x;
    const int r0   = b * RPBB;
    const int w    = tid >> 5;
    const int lane = tid & 31;

    // ---- ONE batched load round: features + labels + G table + consts --------
    float4 x4[4];
#pragma unroll
    for (int r = 0; r < 4; ++r)
        x4[r] = ((const float4*)(f + (size_t)(r0 + w * 4 + r) * DIM))[lane];
    int l32 = 0, l64 = 0;
    if (tid < RPBB) {
        l32 = labw[r0 + tid];
        l64 = labw[(r0 + tid) << 1];
    }
    int acc = labw[2 * tid + 1] | labw[2 * (tid + NT) + 1];
    float gv[8];
#pragma unroll
    for (int j = 0; j < 8; ++j)
        gv[j] = __ldcg(&g_G[0][0] + tid + j * NT);
    float cAl = 0.f, cBe = 0.f, cVl = 0.f;
    if (tid < NCLS) {
        cAl = __ldcg(&g_Al[tid]);
        cBe = __ldcg(&g_Be[tid]);
        cVl = __ldcg(&g_Vl[tid]);
    }

    const int is64 = (__syncthreads_or(acc) == 0);
    if (tid < RPBB) sLab[tid] = (is64 ? l64 : l32) & (NCLS - 1);
#pragma unroll
    for (int j = 0; j < 8; ++j)
        (&sG[0][0])[tid + j * NT] = gv[j];
    if (tid < NCLS) { sAl[tid] = cAl; sBe[tid] = cBe; sVl[tid] = cVl; }
    __syncthreads();

    // ---- warp-per-row loss (4 rows/warp, float4) ------------------------------
    {
        float accL = 0.f, accV = 0.f;
#pragma unroll
        for (int r = 0; r < 4; ++r) {
            const int k = sLab[w * 4 + r];
            const float4 g4 = ((const float4*)&sG[k][0])[lane];
            const float4 x  = x4[r];
            float p = x.x * g4.x; p = fmaf(x.y, g4.y, p);
            p = fmaf(x.z, g4.z, p); p = fmaf(x.w, g4.w, p);
            float q = x.x * x.x; q = fmaf(x.y, x.y, q);
            q = fmaf(x.z, x.z, q); q = fmaf(x.w, x.w, q);
#pragma unroll
            for (int off = 16; off; off >>= 1) {
                p += __shfl_down_sync(0xffffffffu, p, off);
                q += __shfl_down_sync(0xffffffffu, q, off);
            }
            if (lane == 0) {
                const float loss = fmaf(sAl[k], q, sBe[k]) - 2.f * p;
                accL += fmaxf(loss, 0.f) * sVl[k];
                accV += sVl[k];
            }
        }
        if (lane == 0) { sWL[w] = accL; sWV[w] = accV; }
    }
    __syncthreads();

    // ---- tail: elected LAST block reduces and writes out ----------------------
    if (tid == 0) {
        double L = 0.0, V = 0.0;
#pragma unroll
        for (int i = 0; i < 8; ++i) { L += (double)sWL[i]; V += (double)sWV[i]; }
        g_bL[b] = L;
        g_bV[b] = V;
        __threadfence();
        const unsigned tk = atomicAdd(&g_cB, 1u);
        sLast = (((tk + 1u) & (NBB - 1u)) == 0u);   // monotone: replay-safe
    }
    __syncthreads();

    if (sLast) {
        __threadfence();
        double* rL = sR[0];
        double* rV = sR[1];
        if (tid < NBB / 2) {
            rL[tid] = __ldcg(&g_bL[tid]) + __ldcg(&g_bL[tid + NBB / 2]);
            rV[tid] = __ldcg(&g_bV[tid]) + __ldcg(&g_bV[tid + NBB / 2]);
        }
        __syncthreads();
        for (int off = NBB / 4; off; off >>= 1) {
            if (tid < off) { rL[tid] += rL[tid + off]; rV[tid] += rV[tid + off]; }
            __syncthreads();
        }
        if (tid == 0)
            out[0] = (float)(rL[0] / (rV[0] > 1.0 ? rV[0] : 1.0));
    }
}

extern "C" void kernel_launch(void* const* d_in, const int* in_sizes, int n_in,
                              void* d_out, int out_size) {
    const float* f    = (const float*)d_in[0];
    const int*   labw = (const int*)d_in[1];   // int32 or int64 words; detected on-device
    float* out = (float*)d_out;
    kA_stats<<<NBA, NT>>>(f, labw);
    kB_loss <<<NBB, NT>>>(f, labw, out);
}

// round 10
// speedup vs baseline: 1.5477x; 1.5477x over previous
#include <cuda_runtime.h>

#define NT    256
#define NCLS  16
#define DIM   128
#define NR    8192
#define NBA   128
#define RPA   (NR / NBA)     // 64 rows per A-block
#define HPA   (RPA / 2)      // 32 feature values held per thread
#define NBB   256
#define RPBB  (NR / NBB)     // 32 rows per B-block
#define EPS   1e-6
#define MARGIN 10.0
#define SCALE_F 4294967296.0           // 2^32 fixed-point scale for Fsum
#define INV_F   (1.0 / 4294967296.0)
#define SCALE_S 16777216.0             // 2^24 for sum-of-squares
#define INV_S   (1.0 / 16777216.0)

// ---- persistent scratch (no allocation allowed) ----
__device__ unsigned long long g_aF[NCLS][DIM];  // fixed-point class feature sums
__device__ unsigned long long g_aS[NCLS];       // fixed-point class sum-of-squares
__device__ int      g_aC[NCLS];                 // class counts
__device__ unsigned g_c2;                       // tail election counter (monotone)
__device__ double   g_bL[NBB], g_bV[NBB];       // per-block loss/valid partials

// ============================ kernel A: class stats =========================
__global__ void __launch_bounds__(NT)
kA_stats(const float* __restrict__ f, const int* __restrict__ labw) {
    __shared__ float s1[2][NCLS][DIM];
    __shared__ float s2[2][NCLS][DIM];
    __shared__ int   sLab[RPA];
    __shared__ float sPS[NCLS][8];
    __shared__ int   sPC[NCLS][8];

    const int tid = threadIdx.x;
    const int b   = blockIdx.x;
    const int r0  = b * RPA;
    const int dim = tid & (DIM - 1);
    const int h   = tid >> 7;

    // one dependent DRAM round: features + detect words + both label layouts
    float v[HPA];
#pragma unroll
    for (int it = 0; it < HPA; ++it)
        v[it] = f[(size_t)(r0 + 2 * it + h) * DIM + dim];
    int l32 = 0, l64 = 0;
    if (tid < RPA) {
        l32 = labw[r0 + tid];
        l64 = labw[(r0 + tid) << 1];
    }
    int acc = labw[2 * tid + 1] | labw[2 * (tid + NT) + 1];
    const int is64 = (__syncthreads_or(acc) == 0);
    if (tid < RPA) sLab[tid] = (is64 ? l64 : l32) & (NCLS - 1);
    for (int i = tid; i < 2 * NCLS * DIM; i += NT) {
        (&s1[0][0][0])[i] = 0.f;
        (&s2[0][0][0])[i] = 0.f;
    }
    __syncthreads();

    // per-block class partials
#pragma unroll
    for (int it = 0; it < HPA; ++it) {
        const int k = sLab[2 * it + h];
        s1[h][k][dim] += v[it];
        s2[h][k][dim] = fmaf(v[it], v[it], s2[h][k][dim]);
    }
    __syncthreads();

    // exact fixed-point commit (spread addresses; integer atomics => deterministic)
    if (tid < DIM) {
#pragma unroll
        for (int k = 0; k < NCLS; ++k) {
            const double p = (double)(s1[0][k][tid] + s1[1][k][tid]);
            atomicAdd(&g_aF[k][tid], (unsigned long long)__double2ll_rn(p * SCALE_F));
        }
    } else {
        const int t = tid - DIM, k = t >> 3, part = t & 7;
        float s = 0.f;
#pragma unroll
        for (int d = 0; d < 16; ++d) {
            const int dd = part * 16 + d;
            s += s2[0][k][dd] + s2[1][k][dd];
        }
        sPS[k][part] = s;
        int c = 0;
#pragma unroll
        for (int r = 0; r < 8; ++r) c += (sLab[part * 8 + r] == k);
        sPC[k][part] = c;
    }
    __syncthreads();
    if (tid < NCLS) {
        float s = 0.f; int c = 0;
#pragma unroll
        for (int p = 0; p < 8; ++p) { s += sPS[tid][p]; c += sPC[tid][p]; }
        atomicAdd(&g_aS[tid], (unsigned long long)__double2ll_rn((double)s * SCALE_S));
        atomicAdd(&g_aC[tid], c);
    }
}

// ======================= kernel B: per-row loss + reduce ====================
__global__ void __launch_bounds__(NT)
kB_loss(const float* __restrict__ f, const int* __restrict__ labw,
        float* __restrict__ out) {
    __shared__ __align__(16) float sF[NCLS][DIM];   // Fs copy | tail: rL doubles
    __shared__ __align__(16) float sG[NCLS][DIM];   //          | tail: rV doubles
    __shared__ float sTot[DIM];
    __shared__ float sAl[NCLS], sBe[NCLS], sAv[NCLS], sBv[NCLS], sSq[NCLS];
    __shared__ int   sCt[NCLS];
    __shared__ int   sLab[RPBB];
    __shared__ float sWL[8], sWV[8];
    __shared__ double sSqTotD;
    __shared__ int   sLast;

    const int tid  = threadIdx.x;
    const int b    = blockIdx.x;
    const int r0   = b * RPBB;
    const int w    = tid >> 5;
    const int lane = tid & 31;

    // issue independent loads first: features (L2-resident from kA) + labels
    float4 x4[4];
#pragma unroll
    for (int r = 0; r < 4; ++r)
        x4[r] = ((const float4*)(f + (size_t)(r0 + w * 4 + r) * DIM))[lane];
    int l32 = 0, l64 = 0;
    if (tid < RPBB) {
        l32 = labw[r0 + tid];
        l64 = labw[(r0 + tid) << 1];
    }
    int acc = labw[2 * tid + 1] | labw[2 * (tid + NT) + 1];
    const int is64 = (__syncthreads_or(acc) == 0);
    if (tid < RPBB) sLab[tid] = (is64 ? l64 : l32) & (NCLS - 1);

    // class stats from L2 (written by kA; graph edge orders the kernels)
    for (int i = tid; i < NCLS * DIM; i += NT) {
        const long long a = (long long)__ldcg(&g_aF[0][0] + i);
        (&sF[0][0])[i] = (float)((double)a * INV_F);
    }
    if (tid < NCLS) {
        sSq[tid] = (float)((double)(long long)__ldcg(&g_aS[tid]) * INV_S);
        sCt[tid] = __ldcg(&g_aC[tid]);
    }
    __syncthreads();
    if (tid < DIM) {
        float t = 0.f;
#pragma unroll
        for (int k = 0; k < NCLS; ++k) t += sF[k][tid];
        sTot[tid] = t;
    } else if (tid == NT - 1) {
        double st = 0.0;
#pragma unroll
        for (int k = 0; k < NCLS; ++k) st += (double)sSq[k];
        sSqTotD = st;
    }
    __syncthreads();
    if (tid < NCLS) {
        const double cnt = (double)sCt[tid];
        const double c   = cnt - 1.0;
        const double Bv  = 1.0 / ((double)NR - c - 1.0 + EPS);
        const double Av  = 1.0 / (c + EPS) + Bv;
        sAv[tid] = (float)Av;
        sBv[tid] = (float)Bv;
        sAl[tid] = (float)(cnt * Av - (double)NR * Bv);
        sBe[tid] = (float)((double)sSq[tid] * Av - sSqTotD * Bv + MARGIN);
    }
    __syncthreads();
    for (int i = tid; i < NCLS * DIM; i += NT) {
        const int k = i >> 7, d = i & (DIM - 1);
        sG[k][d] = sAv[k] * sF[k][d] - sBv[k] * sTot[d];
    }
    __syncthreads();

    // warp-per-row loss (4 rows/warp, float4)
    {
        float accL = 0.f, accV = 0.f;
#pragma unroll
        for (int r = 0; r < 4; ++r) {
            const int k = sLab[w * 4 + r];
            const float4 g4 = ((const float4*)&sG[k][0])[lane];
            const float4 x  = x4[r];
            float p = x.x * g4.x; p = fmaf(x.y, g4.y, p);
            p = fmaf(x.z, g4.z, p); p = fmaf(x.w, g4.w, p);
            float q = x.x * x.x; q = fmaf(x.y, x.y, q);
            q = fmaf(x.z, x.z, q); q = fmaf(x.w, x.w, q);
#pragma unroll
            for (int off = 16; off; off >>= 1) {
                p += __shfl_down_sync(0xffffffffu, p, off);
                q += __shfl_down_sync(0xffffffffu, q, off);
            }
            if (lane == 0) {
                const float loss  = fmaf(sAl[k], q, sBe[k]) - 2.f * p;
                const float valid = (sCt[k] > 1) ? 1.f : 0.f;
                accL += fmaxf(loss, 0.f) * valid;
                accV += valid;
            }
        }
        if (lane == 0) { sWL[w] = accL; sWV[w] = accV; }
    }
    __syncthreads();

    // tail: elected LAST block reduces, writes out, re-zeroes accumulators
    if (tid == 0) {
        double L = 0.0, V = 0.0;
#pragma unroll
        for (int i = 0; i < 8; ++i) { L += (double)sWL[i]; V += (double)sWV[i]; }
        g_bL[b] = L;
        g_bV[b] = V;
        __threadfence();
        const unsigned tk = atomicAdd(&g_c2, 1u);
        sLast = (((tk + 1u) & (NBB - 1u)) == 0u);   // monotone: replay-safe
    }
    __syncthreads();

    if (sLast) {
        __threadfence();
        // all blocks have read stats and written partials by now: safe to reset
        for (int i = tid; i < NCLS * DIM; i += NT) (&g_aF[0][0])[i] = 0ull;
        if (tid < NCLS) { g_aS[tid] = 0ull; g_aC[tid] = 0; }
        double* rL = reinterpret_cast<double*>(&sF[0][0]);  // reuse smem (8KB)
        double* rV = reinterpret_cast<double*>(&sG[0][0]);
        rL[tid] = __ldcg(&g_bL[tid]);
        rV[tid] = __ldcg(&g_bV[tid]);
        __syncthreads();
        for (int off = NBB / 2; off; off >>= 1) {
            if (tid < off) { rL[tid] += rL[tid + off]; rV[tid] += rV[tid + off]; }
            __syncthreads();
        }
        if (tid == 0)
            out[0] = (float)(rL[0] / (rV[0] > 1.0 ? rV[0] : 1.0));
    }
}

extern "C" void kernel_launch(void* const* d_in, const int* in_sizes, int n_in,
                              void* d_out, int out_size) {
    const float* f    = (const float*)d_in[0];
    const int*   labw = (const int*)d_in[1];   // int32 or int64 words; detected on-device
    float* out = (float*)d_out;
    kA_stats<<<NBA, NT>>>(f, labw);
    kB_loss <<<NBB, NT>>>(f, labw, out);
}